// round 9
// baseline (speedup 1.0000x reference)
#include <cuda_runtime.h>
#include <cuda_fp16.h>
#include <cstdint>

#define NPOS 16384   // 128*128 guide positions
#define LPOS 1024    // 32*32 low positions
#define DMODEL 512

// ---------------------------------------------------------------------------
// Scratch (static device globals — no allocation APIs allowed)
// ---------------------------------------------------------------------------
__device__ __half g_Af [NPOS * DMODEL];          // fp16 activations (guide, then msg)
__device__ __half g_Lf [LPOS * DMODEL];          // fp16 low activations
__device__ __half g_Whi[4 * DMODEL * DMODEL];    // weight hi (fp16)
__device__ __half g_Wlo[4 * DMODEL * DMODEL];    // weight lo (fp16 residual)
__device__ float g_Q [NPOS * DMODEL];
__device__ float g_K [LPOS * DMODEL];
__device__ float g_V [LPOS * DMODEL];
__device__ float g_M2[NPOS * DMODEL];

// ---------------------------------------------------------------------------
// Baseline-PTX helpers (sm_80+ features only: work on plain sm_103 target)
// ---------------------------------------------------------------------------
__device__ __forceinline__ uint32_t smem_u32(const void* p) {
    uint32_t a;
    asm("{ .reg .u64 t; cvta.to.shared.u64 t, %1; cvt.u32.u64 %0, t; }" : "=r"(a) : "l"(p));
    return a;
}

#define CP16(dst, src) \
    asm volatile("cp.async.cg.shared.global [%0], [%1], 16;" :: "r"(dst), "l"(src))
#define CP_COMMIT() asm volatile("cp.async.commit_group;" ::: "memory")
#define CP_WAIT(n)  asm volatile("cp.async.wait_group %0;" :: "n"(n) : "memory")

#define LDSM4(r0, r1, r2, r3, addr) \
    asm volatile("ldmatrix.sync.aligned.m8n8.x4.shared.b16 {%0,%1,%2,%3}, [%4];" \
        : "=r"(r0), "=r"(r1), "=r"(r2), "=r"(r3) : "r"(addr))

#define MMA16816F(d, a, b0, b1) \
    asm volatile("mma.sync.aligned.m16n8k16.row.col.f32.f16.f16.f32 " \
        "{%0,%1,%2,%3}, {%4,%5,%6,%7}, {%8,%9}, {%0,%1,%2,%3};" \
        : "+f"((d)[0]), "+f"((d)[1]), "+f"((d)[2]), "+f"((d)[3]) \
        : "r"((a)[0]), "r"((a)[1]), "r"((a)[2]), "r"((a)[3]), \
          "r"(b0), "r"(b1))

// ---------------------------------------------------------------------------
// mma_gemm: C[m][n] = sum_k A[m][k]*B[n][k], K=512 fixed.
// fp32 emulation: A rounded to fp16, B = Bhi + Blo fp16 split (exact):
//   C = A*Bhi + A*Blo, fp32 accumulate.
// CTA: 128x128 tile, 128 threads = 4 warps (2m x 2n), warp tile 64x64.
// K chunks of 32, 3 smem buffers, single barrier per chunk.
// Compute is software-pipelined at the column-pair level: the LDSM4s for
// b-pair p+1 are issued BEFORE the MMAs of pair p (ping-pong b buffers),
// so b-fragment latency hides inside the MMA bursts; only the a-frags and
// the first b-pair per k16 are exposed.
// Three independent GEMMs selected by blockIdx.z; CTAs with
// blockIdx.y >= mtiles exit immediately (QKV share one launch).
// ---------------------------------------------------------------------------
#define PITCH 80
#define TILE_B (128 * PITCH)            // 10240 B per operand tile
#define STAGE_B (3 * TILE_B)            // A, Bhi, Blo = 30720 B per stage
#define NSTAGE 3

struct GemmArgs {
    const __half* A;
    const __half* Bhi;
    const __half* Blo;
    float* C;
    int mtiles;
};

__global__ __launch_bounds__(128, 2)
void mma_gemm(GemmArgs g0, GemmArgs g1, GemmArgs g2)
{
    const GemmArgs& ga_ = (blockIdx.z == 0) ? g0 : (blockIdx.z == 1) ? g1 : g2;
    if ((int)blockIdx.y >= ga_.mtiles) return;

    const __half* __restrict__ A   = ga_.A;
    const __half* __restrict__ Bhi = ga_.Bhi;
    const __half* __restrict__ Blo = ga_.Blo;
    float* __restrict__ C = ga_.C;

    extern __shared__ char smem[];
    const uint32_t sb = smem_u32(smem);

    const int tid  = threadIdx.x;
    const int wid  = tid >> 5;
    const int lane = tid & 31;
    const int bm0  = blockIdx.y * 128;
    const int bn0  = blockIdx.x * 128;
    const int wm   = (wid >> 1) * 64;    // warp m offset in tile
    const int wn   = (wid & 1) * 64;     // warp n offset in tile

    float acc[4][8][4];
#pragma unroll
    for (int i = 0; i < 4; i++)
#pragma unroll
        for (int j = 0; j < 8; j++)
#pragma unroll
            for (int r = 0; r < 4; r++) acc[i][j][r] = 0.f;

    // ---- async stage loader: 12 x 16B per thread per stage
    auto load_stage = [&](int s, int k0) {
        const uint32_t base = sb + s * STAGE_B;
#pragma unroll
        for (int i = 0; i < 4; i++) {
            const int idx = tid + 128 * i;        // 0..511
            const int row = idx >> 2;             // 0..127
            const int c   = idx & 3;              // 16B chunk in 64B row
            const uint32_t off = row * PITCH + c * 16;
            const size_t ga = ((size_t)(bm0 + row) * 512 + k0) * 2 + c * 16;
            const size_t gb = ((size_t)(bn0 + row) * 512 + k0) * 2 + c * 16;
            CP16(base + off,              (const char*)A   + ga);
            CP16(base + TILE_B + off,     (const char*)Bhi + gb);
            CP16(base + 2 * TILE_B + off, (const char*)Blo + gb);
        }
        CP_COMMIT();
    };

    // ---- compute one k32 chunk from stage s (pipelined b-pair LDSM)
    auto compute_stage = [&](int s) {
        const uint32_t base = sb + s * STAGE_B;
#pragma unroll
        for (int kk = 0; kk < 2; kk++) {          // two k16 halves
            const uint32_t koff = kk * 32;        // byte offset of k16 half

            uint32_t a[4][4];
#pragma unroll
            for (int f = 0; f < 4; f++) {
                const uint32_t ra = base +
                    (uint32_t)(wm + f * 16 + (lane & 15)) * PITCH +
                    koff + ((lane >> 4) << 4);
                LDSM4(a[f][0], a[f][1], a[f][2], a[f][3], ra);
            }

            // ping-pong b fragments: [buf][4 regs] = two n8 groups per pair
            uint32_t bh[2][4], bl[2][4];
            auto ldb = [&](int p, int buf) {
                const uint32_t rb = base + TILE_B +
                    (uint32_t)(wn + p * 16 + (lane & 7) + ((lane >> 4) << 3)) * PITCH +
                    koff + (((lane >> 3) & 1) << 4);
                LDSM4(bh[buf][0], bh[buf][1], bh[buf][2], bh[buf][3], rb);
                LDSM4(bl[buf][0], bl[buf][1], bl[buf][2], bl[buf][3], rb + TILE_B);
            };

            ldb(0, 0);
#pragma unroll
            for (int p = 0; p < 4; p++) {
                if (p < 3) ldb(p + 1, (p + 1) & 1);   // prefetch next pair
                const int b = p & 1;
#pragma unroll
                for (int f = 0; f < 4; f++) {
                    MMA16816F(acc[f][2 * p],     a[f], bh[b][0], bh[b][1]);
                    MMA16816F(acc[f][2 * p],     a[f], bl[b][0], bl[b][1]);
                    MMA16816F(acc[f][2 * p + 1], a[f], bh[b][2], bh[b][3]);
                    MMA16816F(acc[f][2 * p + 1], a[f], bl[b][2], bl[b][3]);
                }
            }
        }
    };

    // ---- prologue: 2 chunks in flight
    load_stage(0, 0);
    load_stage(1, 32);

#pragma unroll
    for (int c = 0; c < 16; c++) {
        if (c < 15) { CP_WAIT(1); } else { CP_WAIT(0); }
        __syncthreads();
        if (c + 2 < 16) load_stage((c + 2) % NSTAGE, (c + 2) * 32);
        compute_stage(c % NSTAGE);
    }

    // ---- epilogue: acc -> C (fp32, row stride 512)
    const int qrow = lane >> 2;          // 0..7
    const int qcol = (lane & 3) * 2;     // 0,2,4,6
#pragma unroll
    for (int f = 0; f < 4; f++)
#pragma unroll
        for (int g = 0; g < 8; g++) {
            const int row = bm0 + wm + f * 16 + qrow;
            const int col = bn0 + wn + g * 8 + qcol;
            *(float2*)(C + (size_t)row * 512 + col) =
                make_float2(acc[f][g][0], acc[f][g][1]);
            *(float2*)(C + (size_t)(row + 8) * 512 + col) =
                make_float2(acc[f][g][2], acc[f][g][3]);
        }
}

// ---------------------------------------------------------------------------
// convT: in fp32 [512][M] (channel-major) -> fp16 [M][512] (transpose+round).
// ---------------------------------------------------------------------------
__global__ __launch_bounds__(256)
void convT_kernel(const float* __restrict__ in, __half* __restrict__ outp, int M)
{
    __shared__ float t[32][33];
    const int tx = threadIdx.x, ty = threadIdx.y;
    const int mb = blockIdx.x * 32, kb = blockIdx.y * 32;
#pragma unroll
    for (int j = 0; j < 4; j++)
        t[ty + 8 * j][tx] = in[(size_t)(kb + ty + 8 * j) * M + mb + tx];
    __syncthreads();
#pragma unroll
    for (int j = 0; j < 4; j++) {
        const float v = t[tx][ty + 8 * j];
        outp[(size_t)(mb + ty + 8 * j) * 512 + kb + tx] = __float2half(v);
    }
}

// ---------------------------------------------------------------------------
// conv_w: all 4 weights in one launch (blockIdx.z selects). fp32 -> hi/lo fp16.
// ---------------------------------------------------------------------------
__global__ __launch_bounds__(256)
void conv_w_kernel(const float4* __restrict__ w0, const float4* __restrict__ w1,
                   const float4* __restrict__ w2, const float4* __restrict__ w3,
                   __half* __restrict__ whi, __half* __restrict__ wlo)
{
    const int z = blockIdx.z;
    const float4* src = (z == 0) ? w0 : (z == 1) ? w1 : (z == 2) ? w2 : w3;
    const int i = blockIdx.x * 256 + threadIdx.x;        // 0..65535
    const float4 v = src[i];

    const __half hx = __float2half(v.x), hy = __float2half(v.y);
    const __half hz = __float2half(v.z), hw = __float2half(v.w);
    const __half lx = __float2half(v.x - __half2float(hx));
    const __half ly = __float2half(v.y - __half2float(hy));
    const __half lz = __float2half(v.z - __half2float(hz));
    const __half lw = __float2half(v.w - __half2float(hw));

    const size_t o = (size_t)z * (DMODEL * DMODEL / 4) + i;
    ((ushort4*)whi)[o] = make_ushort4(__half_as_ushort(hx), __half_as_ushort(hy),
                                      __half_as_ushort(hz), __half_as_ushort(hw));
    ((ushort4*)wlo)[o] = make_ushort4(__half_as_ushort(lx), __half_as_ushort(ly),
                                      __half_as_ushort(lz), __half_as_ushort(lw));
}

// ---------------------------------------------------------------------------
// Windowed attention, 256 threads: tid = head*32 + half*16 + pos.
// (pos,head) pair splits the 64-elem head dim across two same-warp threads
// (shfl_xor 16 combines score partials); each thread emits 32 out channels.
// One block per 4x4 guide tile (shared 3x3 window). Writes fp16.
// ---------------------------------------------------------------------------
__global__ __launch_bounds__(256)
void attn_kernel(const float* __restrict__ Q, const float* __restrict__ Km,
                 const float* __restrict__ Vm, __half* __restrict__ msg)
{
    __shared__ float Ks[9][512];
    __shared__ float Vs[9][512];

    const int tx = blockIdx.x;
    const int ty = blockIdx.y;
    const int tid = threadIdx.x;

    for (int idx = tid; idx < 9 * 128; idx += 256) {
        const int k  = idx >> 7;
        const int c4 = idx & 127;
        const int yy = min(max(ty - 1 + k / 3, 0), 31);
        const int xx = min(max(tx - 1 + k % 3, 0), 31);
        const int p  = yy * 32 + xx;
        ((float4*)&Ks[k][0])[c4] = ((const float4*)(Km + (size_t)p * 512))[c4];
        ((float4*)&Vs[k][0])[c4] = ((const float4*)(Vm + (size_t)p * 512))[c4];
    }
    __syncthreads();

    const int pos  = tid & 15;           // 0..15
    const int half = (tid >> 4) & 1;     // 0..1
    const int head = tid >> 5;           // 0..7
    const int n = (ty * 4 + (pos >> 2)) * 128 + tx * 4 + (pos & 3);
    const int coff = head * 64 + half * 32;   // this thread's 32 channels

    const float4* q4 = (const float4*)(Q + (size_t)n * 512 + coff);

    float acc[9];
#pragma unroll
    for (int k = 0; k < 9; k++) acc[k] = 0.f;

#pragma unroll
    for (int e = 0; e < 8; e++) {
        float4 qv = q4[e];
#pragma unroll
        for (int k = 0; k < 9; k++) {
            float4 kv = ((const float4*)&Ks[k][coff])[e];
            acc[k] += qv.x * kv.x + qv.y * kv.y + qv.z * kv.z + qv.w * kv.w;
        }
    }
    // combine the two halves (threads tid and tid^16 share a warp)
#pragma unroll
    for (int k = 0; k < 9; k++)
        acc[k] += __shfl_xor_sync(0xffffffffu, acc[k], 16);

    float mx = acc[0];
#pragma unroll
    for (int k = 1; k < 9; k++) mx = fmaxf(mx, acc[k]);
    float s = 0.f;
#pragma unroll
    for (int k = 0; k < 9; k++) { acc[k] = __expf(0.125f * (acc[k] - mx)); s += acc[k]; }
    const float inv = 1.f / s;
#pragma unroll
    for (int k = 0; k < 9; k++) acc[k] *= inv;

    __half* outp = msg + (size_t)n * 512 + coff;
#pragma unroll
    for (int e = 0; e < 8; e++) {
        float4 o = make_float4(0.f, 0.f, 0.f, 0.f);
#pragma unroll
        for (int k = 0; k < 9; k++) {
            float4 vv = ((const float4*)&Vs[k][coff])[e];
            o.x += acc[k] * vv.x;
            o.y += acc[k] * vv.y;
            o.z += acc[k] * vv.z;
            o.w += acc[k] * vv.w;
        }
        const __half2 h0 = __floats2half2_rn(o.x, o.y);
        const __half2 h1 = __floats2half2_rn(o.z, o.w);
        uint2 pk;
        pk.x = *(const uint32_t*)&h0;
        pk.y = *(const uint32_t*)&h1;
        *(uint2*)(outp + e * 4) = pk;
    }
}

// ---------------------------------------------------------------------------
// LayerNorm over d=512 per position + transpose to channel-major output.
// ---------------------------------------------------------------------------
__global__ __launch_bounds__(256)
void ln_kernel(const float* __restrict__ X, const float* __restrict__ gamma,
               const float* __restrict__ beta, float* __restrict__ out)
{
    __shared__ float sm[16 * 513];

    const int nb   = blockIdx.x * 16;
    const int warp = threadIdx.x >> 5;
    const int lane = threadIdx.x & 31;

    for (int r = warp; r < 16; r += 8) {
        const int n = nb + r;
        const float* row = X + (size_t)n * 512;
        float v[16];
        float s = 0.f;
#pragma unroll
        for (int j = 0; j < 16; j++) { v[j] = row[lane + 32 * j]; s += v[j]; }
#pragma unroll
        for (int o = 16; o > 0; o >>= 1) s += __shfl_xor_sync(0xffffffffu, s, o);
        const float mu = s * (1.f / 512.f);
        float q = 0.f;
#pragma unroll
        for (int j = 0; j < 16; j++) { float d = v[j] - mu; q += d * d; }
#pragma unroll
        for (int o = 16; o > 0; o >>= 1) q += __shfl_xor_sync(0xffffffffu, q, o);
        const float rstd = rsqrtf(q * (1.f / 512.f) + 1e-5f);
#pragma unroll
        for (int j = 0; j < 16; j++) {
            const int o = lane + 32 * j;
            sm[r * 513 + o] = (v[j] - mu) * rstd * gamma[o] + beta[o];
        }
    }
    __syncthreads();

    const int i  = threadIdx.x & 15;
    const int ob = threadIdx.x >> 4;
    for (int o = ob; o < 512; o += 16)
        out[(size_t)o * 16384 + nb + i] = sm[i * 513 + o];
}

// ---------------------------------------------------------------------------
extern "C" void kernel_launch(void* const* d_in, const int* in_sizes, int n_in,
                              void* d_out, int out_size)
{
    const float* low   = (const float*)d_in[0];
    const float* guide = (const float*)d_in[1];
    const float* Wq    = (const float*)d_in[2];
    const float* Wk    = (const float*)d_in[3];
    const float* Wv    = (const float*)d_in[4];
    const float* Wm    = (const float*)d_in[5];
    const float* gamma = (const float*)d_in[6];
    const float* beta  = (const float*)d_in[7];
    float* out = (float*)d_out;

    __half *Af, *Lf, *Whi, *Wlo;
    float *Q, *K, *V, *M2;
    cudaGetSymbolAddress((void**)&Af,  g_Af);
    cudaGetSymbolAddress((void**)&Lf,  g_Lf);
    cudaGetSymbolAddress((void**)&Whi, g_Whi);
    cudaGetSymbolAddress((void**)&Wlo, g_Wlo);
    cudaGetSymbolAddress((void**)&Q,   g_Q);
    cudaGetSymbolAddress((void**)&K,   g_K);
    cudaGetSymbolAddress((void**)&V,   g_V);
    cudaGetSymbolAddress((void**)&M2,  g_M2);

    const int W_ELEMS = DMODEL * DMODEL;       // 262144
    const int GEMM_SMEM = NSTAGE * STAGE_B;    // 92160 B

    cudaFuncSetAttribute(mma_gemm, cudaFuncAttributeMaxDynamicSharedMemorySize,
                         GEMM_SMEM);

    // Convert + transpose activations (channel-major fp32 -> row-major fp16)
    convT_kernel<<<dim3(NPOS / 32, 16), dim3(32, 8)>>>(guide, Af, NPOS);
    convT_kernel<<<dim3(LPOS / 32, 16), dim3(32, 8)>>>(low, Lf, LPOS);

    // Convert all 4 weights in one launch: slots 0=Wq, 1=Wk, 2=Wv, 3=Wm
    conv_w_kernel<<<dim3(W_ELEMS / 4 / 256, 1, 4), 256>>>(
        (const float4*)Wq, (const float4*)Wk, (const float4*)Wv, (const float4*)Wm,
        Whi, Wlo);

    // Q, K, V projections in ONE launch (z selects; y-overrun CTAs exit)
    {
        GemmArgs gq = { Af, Whi,               Wlo,               Q, 128 };
        GemmArgs gk = { Lf, Whi + 1 * W_ELEMS, Wlo + 1 * W_ELEMS, K, 8 };
        GemmArgs gv = { Lf, Whi + 2 * W_ELEMS, Wlo + 2 * W_ELEMS, V, 8 };
        mma_gemm<<<dim3(4, 128, 3), 128, GEMM_SMEM>>>(gq, gk, gv);
    }

    // Windowed attention -> fp16 msg directly into Af (guide no longer needed)
    attn_kernel<<<dim3(32, 32), 256>>>(Q, K, V, Af);

    // M2 = msg @ Wm^T
    {
        GemmArgs gm = { Af, Whi + 3 * W_ELEMS, Wlo + 3 * W_ELEMS, M2, 128 };
        mma_gemm<<<dim3(4, 128, 1), 128, GEMM_SMEM>>>(gm, gm, gm);
    }

    // LayerNorm + transpose to channel-major output
    ln_kernel<<<1024, 256>>>(M2, gamma, beta, out);
}